// round 12
// baseline (speedup 1.0000x reference)
#include <cuda_runtime.h>
#include <cuda_bf16.h>
#include <cstdint>

// Problem constants: N_VOXELS=80000, C=64, NX=NY=512, B=4
#define NXC    512
#define NYC    512
#define CCH    64
#define BATCHN 4
#define PLANE  (NXC * NYC)            // 262144 spatial slots per batch
#define SLOTS  (BATCHN * PLANE)       // 1048576 total slots
#define PQ     (PLANE / 4)            // 65536 float4-quads per (b,c) plane
#define QTOT   (SLOTS / 4)            // 262144 slot-quads (2^18)
#define KCH    8                      // channels per thread
#define NCG    (CCH / KCH)            // 8 channel groups
#define QPB    32                     // quads per block (block = QPB * NCG = 256 thr)

// Per-slot winner: 0 = empty, else (voxel_index + 1).
// Zero-initialized at module load; gather restores all-zeros after reading,
// so "winner == 0 everywhere" holds at every kernel_launch / graph replay.
__device__ int g_winner[SLOTS];
// Zero row for branchless empty-slot loads (never written).
__device__ float4 g_zero4[2];

// ---------------------------------------------------------------------------
// Kernel 1: last-write-wins vote. atomicMax over (voxel_index + 1) => highest
// voxel index wins each slot (deterministic serial-scatter semantics).
// ---------------------------------------------------------------------------
__global__ void vote_kernel(const int* __restrict__ coords, int n) {
    int i = blockIdx.x * blockDim.x + threadIdx.x;
    if (i < n) {
        int b = coords[3 * i + 0];
        int x = coords[3 * i + 1];
        int y = coords[3 * i + 2];
        atomicMax(&g_winner[b * PLANE + x * NYC + y], i + 1);
    }
}

// ---------------------------------------------------------------------------
// Kernel 2: gather + self-reset, tuned for occupancy.
// Block = 256 threads = 32 consecutive slot-quads x 8 channel-groups.
// Two 4-channel phases keep live registers low (launch_bounds forces >=6
// blocks/SM). Winner staged once in smem (4 MB total), reset immediately by
// the loading thread (exclusive block ownership). Output stores are fully
// coalesced 512B warp transactions via __stcs (streaming; keeps the 20 MB
// feature array resident in L2).
// ---------------------------------------------------------------------------
__global__ void __launch_bounds__(256, 6)
gather_kernel(const float* __restrict__ feat, float* __restrict__ out) {
    __shared__ int4 s_w[QPB];

    unsigned tid   = threadIdx.x;
    unsigned ql    = tid & (QPB - 1);           // quad-in-block 0..31
    unsigned cg    = tid >> 5;                  // channel group 0..7
    unsigned qbase = blockIdx.x * QPB;
    unsigned q     = qbase + ql;                // global slot-quad

    if (tid < QPB) {
        int4 w = ((const int4*)g_winner)[qbase + tid];
        s_w[tid] = w;
        ((int4*)g_winner)[qbase + tid] = make_int4(0, 0, 0, 0);  // restore invariant
    }
    __syncthreads();

    const int4 w4 = s_w[ql];

    unsigned b  = q >> 16;                      // q / PQ (uniform per block)
    unsigned pq = q & (PQ - 1);

    // Branchless row pointers: winner w>0 -> feat row (w-1), else zero buffer
    const float4* z = g_zero4;
    const float4* r0 = (w4.x > 0) ? (const float4*)(feat + (w4.x - 1) * CCH + cg * KCH) : z;
    const float4* r1 = (w4.y > 0) ? (const float4*)(feat + (w4.y - 1) * CCH + cg * KCH) : z;
    const float4* r2 = (w4.z > 0) ? (const float4*)(feat + (w4.z - 1) * CCH + cg * KCH) : z;
    const float4* r3 = (w4.w > 0) ? (const float4*)(feat + (w4.w - 1) * CCH + cg * KCH) : z;

    float4* outq = (float4*)out + (size_t)(b * CCH + cg * KCH) * PQ + pq;

    // Phase 1: channels cg*8 .. cg*8+3
    {
        float4 a = r0[0], e = r1[0], c = r2[0], d = r3[0];
        __stcs(&outq[0 * PQ], make_float4(a.x, e.x, c.x, d.x));
        __stcs(&outq[1 * PQ], make_float4(a.y, e.y, c.y, d.y));
        __stcs(&outq[2 * PQ], make_float4(a.z, e.z, c.z, d.z));
        __stcs(&outq[3 * PQ], make_float4(a.w, e.w, c.w, d.w));
    }
    // Phase 2: channels cg*8+4 .. cg*8+7
    {
        float4 a = r0[1], e = r1[1], c = r2[1], d = r3[1];
        __stcs(&outq[4 * PQ], make_float4(a.x, e.x, c.x, d.x));
        __stcs(&outq[5 * PQ], make_float4(a.y, e.y, c.y, d.y));
        __stcs(&outq[6 * PQ], make_float4(a.z, e.z, c.z, d.z));
        __stcs(&outq[7 * PQ], make_float4(a.w, e.w, c.w, d.w));
    }
}

// ---------------------------------------------------------------------------
extern "C" void kernel_launch(void* const* d_in, const int* in_sizes, int n_in,
                              void* d_out, int out_size) {
    const float* feat   = (const float*)d_in[0];   // [N, 64] fp32
    const int*   coords = (const int*)d_in[1];     // [N, 3]  int32
    const int n = in_sizes[0] / CCH;               // number of voxels

    vote_kernel<<<(n + 255) / 256, 256>>>(coords, n);

    int blocks = QTOT / QPB;                       // 8192 blocks x 256 threads
    gather_kernel<<<blocks, 256>>>(feat, (float*)d_out);
}

// round 14
// speedup vs baseline: 1.1149x; 1.1149x over previous
#include <cuda_runtime.h>
#include <cuda_bf16.h>
#include <cstdint>

// Problem constants: N_VOXELS=80000, C=64, NX=NY=512, B=4
#define NXC    512
#define NYC    512
#define CCH    64
#define BATCHN 4
#define PLANE  (NXC * NYC)            // 262144 spatial slots per batch
#define SLOTS  (BATCHN * PLANE)       // 1048576 total slots
#define PQ     (PLANE / 4)            // 65536 float4-quads per (b,c) plane
#define QTOT   (SLOTS / 4)            // 262144 slot-quads (2^18)
#define KCH    8                      // channels per thread
#define NCG    (CCH / KCH)            // 8 channel groups
#define QPB    16                     // quads per block (block = QPB * NCG = 128 thr)

// Per-slot winner: 0 = empty, else (voxel_index + 1).
// Zero-initialized at module load; gather restores all-zeros after reading,
// so "winner == 0 everywhere" holds at every kernel_launch / graph replay.
__device__ int g_winner[SLOTS];
// Zero row for branchless empty-slot loads (never written).
__device__ float4 g_zero4[2];

// ---------------------------------------------------------------------------
// Kernel 1: last-write-wins vote. atomicMax over (voxel_index + 1) => highest
// voxel index wins each slot (deterministic serial-scatter semantics).
// ---------------------------------------------------------------------------
__global__ void vote_kernel(const int* __restrict__ coords, int n) {
    int i = blockIdx.x * blockDim.x + threadIdx.x;
    if (i < n) {
        int b = coords[3 * i + 0];
        int x = coords[3 * i + 1];
        int y = coords[3 * i + 2];
        atomicMax(&g_winner[b * PLANE + x * NYC + y], i + 1);
    }
}

// ---------------------------------------------------------------------------
// Kernel 2: gather + self-reset. R9 structure restored: all 8 feat loads are
// issued as one batch (MLP=8 per thread — this, not occupancy, is what
// saturates DRAM; the R12 two-phase split proved the opposite direction).
// Block = 128 threads = 16 consecutive slot-quads x 8 channel-groups:
//   - 16 threads stage the block's int4 winners in smem and immediately reset
//     them to 0 (exclusive block ownership; restores the invariant)
//   - each thread gathers 8 channels of 4 slots: 8 batched float4 feat loads
//     (2 consecutive float4 per voxel row; empty slots read warp-uniform
//     g_zero4 — branchless), 4x4 register transposes, 8 coalesced float4
//     streaming stores (__stcs: 256 MB write stream must not thrash L2).
// ---------------------------------------------------------------------------
__global__ void gather_kernel(const float* __restrict__ feat,
                              float* __restrict__ out) {
    __shared__ int4 s_w[QPB];

    unsigned tid   = threadIdx.x;
    unsigned ql    = tid & (QPB - 1);           // quad-in-block 0..15
    unsigned cg    = tid >> 4;                  // channel group 0..7
    unsigned qbase = blockIdx.x * QPB;
    unsigned q     = qbase + ql;                // global slot-quad

    if (tid < QPB) {
        int4 w = ((const int4*)g_winner)[qbase + tid];
        s_w[tid] = w;
        ((int4*)g_winner)[qbase + tid] = make_int4(0, 0, 0, 0);  // restore invariant
    }
    __syncthreads();

    const int4 w4 = s_w[ql];

    unsigned b  = q >> 16;                      // q / PQ
    unsigned pq = q & (PQ - 1);

    // Branchless row pointers: winner w>0 -> feat row (w-1), else zero buffer
    const float4* z = g_zero4;
    const float4* r0 = (w4.x > 0) ? (const float4*)(feat + (w4.x - 1) * CCH + cg * KCH) : z;
    const float4* r1 = (w4.y > 0) ? (const float4*)(feat + (w4.y - 1) * CCH + cg * KCH) : z;
    const float4* r2 = (w4.z > 0) ? (const float4*)(feat + (w4.z - 1) * CCH + cg * KCH) : z;
    const float4* r3 = (w4.w > 0) ? (const float4*)(feat + (w4.w - 1) * CCH + cg * KCH) : z;

    // One batch of 8 independent loads (keep MLP = 8; do NOT split into phases)
    float4 a0 = r0[0], a1 = r0[1];
    float4 b0 = r1[0], b1 = r1[1];
    float4 c0 = r2[0], c1 = r2[1];
    float4 d0 = r3[0], d1 = r3[1];

    float4* outq = (float4*)out + (size_t)(b * CCH + cg * KCH) * PQ + pq;

    __stcs(&outq[0 * PQ], make_float4(a0.x, b0.x, c0.x, d0.x));
    __stcs(&outq[1 * PQ], make_float4(a0.y, b0.y, c0.y, d0.y));
    __stcs(&outq[2 * PQ], make_float4(a0.z, b0.z, c0.z, d0.z));
    __stcs(&outq[3 * PQ], make_float4(a0.w, b0.w, c0.w, d0.w));
    __stcs(&outq[4 * PQ], make_float4(a1.x, b1.x, c1.x, d1.x));
    __stcs(&outq[5 * PQ], make_float4(a1.y, b1.y, c1.y, d1.y));
    __stcs(&outq[6 * PQ], make_float4(a1.z, b1.z, c1.z, d1.z));
    __stcs(&outq[7 * PQ], make_float4(a1.w, b1.w, c1.w, d1.w));
}

// ---------------------------------------------------------------------------
extern "C" void kernel_launch(void* const* d_in, const int* in_sizes, int n_in,
                              void* d_out, int out_size) {
    const float* feat   = (const float*)d_in[0];   // [N, 64] fp32
    const int*   coords = (const int*)d_in[1];     // [N, 3]  int32
    const int n = in_sizes[0] / CCH;               // number of voxels

    vote_kernel<<<(n + 255) / 256, 256>>>(coords, n);

    int blocks = QTOT / QPB;                       // 16384 blocks x 128 threads
    gather_kernel<<<blocks, 128>>>(feat, (float*)d_out);
}

// round 15
// speedup vs baseline: 1.2003x; 1.0766x over previous
#include <cuda_runtime.h>
#include <cuda_bf16.h>
#include <cstdint>

// Problem constants: N_VOXELS=80000, C=64, NX=NY=512, B=4
#define NXC    512
#define NYC    512
#define CCH    64
#define BATCHN 4
#define PLANE  (NXC * NYC)            // 262144 spatial slots per batch
#define SLOTS  (BATCHN * PLANE)       // 1048576 total slots
#define PQ     (PLANE / 4)            // 65536 float4-quads per (b,c) plane
#define QTOT   (SLOTS / 4)            // 262144 slot-quads (2^18)
#define KCH    8                      // channels per thread
#define NCG    (CCH / KCH)            // 8 channel groups
#define QPB    64                     // quads per block (2 per thread, 256 thr)

// Per-slot winner: 0 = empty, else (voxel_index + 1).
// Zero-initialized at module load; gather restores all-zeros after reading,
// so "winner == 0 everywhere" holds at every kernel_launch / graph replay.
__device__ int g_winner[SLOTS];
// Zero row for branchless empty-slot loads (never written).
__device__ float4 g_zero4[2];

// ---------------------------------------------------------------------------
// Kernel 1: last-write-wins vote. atomicMax over (voxel_index + 1) => highest
// voxel index wins each slot (deterministic serial-scatter semantics).
// ---------------------------------------------------------------------------
__global__ void vote_kernel(const int* __restrict__ coords, int n) {
    int i = blockIdx.x * blockDim.x + threadIdx.x;
    if (i < n) {
        int b = coords[3 * i + 0];
        int x = coords[3 * i + 1];
        int y = coords[3 * i + 2];
        atomicMax(&g_winner[b * PLANE + x * NYC + y], i + 1);
    }
}

// ---------------------------------------------------------------------------
// Kernel 2: gather + self-reset. R9 structure (the proven optimum) with the
// per-thread quad count doubled for MLP=16:
//   block = 256 threads = 8 channel-groups x 32 lanes, owning 64 consecutive
//   slot-quads; lane ql processes quads ql (A) and ql+32 (B).
//   - 64 threads stage the block's int4 winners in smem; reset AFTER the
//     barrier (exclusive ownership -> invariant restored for next replay)
//   - each thread issues A's 8 float4 feat loads then B's 8 (16 independent
//     LDG.128 in flight), then stores A's 8 and B's 8 channels.
//   - empty slots read warp-uniform g_zero4 (branchless)
//   - every store: warp = 32 lanes x consecutive pq -> one 512B transaction;
//     __stcs streams the 256 MB output past L2 so feat stays resident.
// ---------------------------------------------------------------------------
__global__ void __launch_bounds__(256)
gather_kernel(const float* __restrict__ feat, float* __restrict__ out) {
    __shared__ int4 s_w[QPB];

    unsigned tid   = threadIdx.x;
    unsigned ql    = tid & 31;                  // lane-quad 0..31
    unsigned cg    = tid >> 5;                  // channel group 0..7
    unsigned qbase = blockIdx.x * QPB;

    if (tid < QPB) {
        s_w[tid] = ((const int4*)g_winner)[qbase + tid];
    }
    __syncthreads();
    if (tid < QPB) {
        ((int4*)g_winner)[qbase + tid] = make_int4(0, 0, 0, 0);  // restore invariant
    }

    const int4 wA = s_w[ql];
    const int4 wB = s_w[ql + 32];

    unsigned qA = qbase + ql;                   // quad A
    unsigned b  = qA >> 16;                     // batch (uniform across block:
    unsigned pq = qA & (PQ - 1);                //  qbase%64==0, PQ%64==0)

    const float4* z = g_zero4;
    unsigned cgo = cg * KCH;

    // Row pointers for both quads (branchless zero redirect)
    const float4* a0p = (wA.x > 0) ? (const float4*)(feat + (wA.x - 1) * CCH + cgo) : z;
    const float4* a1p = (wA.y > 0) ? (const float4*)(feat + (wA.y - 1) * CCH + cgo) : z;
    const float4* a2p = (wA.z > 0) ? (const float4*)(feat + (wA.z - 1) * CCH + cgo) : z;
    const float4* a3p = (wA.w > 0) ? (const float4*)(feat + (wA.w - 1) * CCH + cgo) : z;
    const float4* b0p = (wB.x > 0) ? (const float4*)(feat + (wB.x - 1) * CCH + cgo) : z;
    const float4* b1p = (wB.y > 0) ? (const float4*)(feat + (wB.y - 1) * CCH + cgo) : z;
    const float4* b2p = (wB.z > 0) ? (const float4*)(feat + (wB.z - 1) * CCH + cgo) : z;
    const float4* b3p = (wB.w > 0) ? (const float4*)(feat + (wB.w - 1) * CCH + cgo) : z;

    // 16 independent loads, all issued before any store (MLP = 16)
    float4 A00 = a0p[0], A01 = a0p[1];
    float4 A10 = a1p[0], A11 = a1p[1];
    float4 A20 = a2p[0], A21 = a2p[1];
    float4 A30 = a3p[0], A31 = a3p[1];
    float4 B00 = b0p[0], B01 = b0p[1];
    float4 B10 = b1p[0], B11 = b1p[1];
    float4 B20 = b2p[0], B21 = b2p[1];
    float4 B30 = b3p[0], B31 = b3p[1];

    float4* outq = (float4*)out + (size_t)(b * CCH + cgo) * PQ + pq;

    // Quad A stores (channels cgo..cgo+7), each a full 512B warp transaction
    __stcs(&outq[0 * PQ], make_float4(A00.x, A10.x, A20.x, A30.x));
    __stcs(&outq[1 * PQ], make_float4(A00.y, A10.y, A20.y, A30.y));
    __stcs(&outq[2 * PQ], make_float4(A00.z, A10.z, A20.z, A30.z));
    __stcs(&outq[3 * PQ], make_float4(A00.w, A10.w, A20.w, A30.w));
    __stcs(&outq[4 * PQ], make_float4(A01.x, A11.x, A21.x, A31.x));
    __stcs(&outq[5 * PQ], make_float4(A01.y, A11.y, A21.y, A31.y));
    __stcs(&outq[6 * PQ], make_float4(A01.z, A11.z, A21.z, A31.z));
    __stcs(&outq[7 * PQ], make_float4(A01.w, A11.w, A21.w, A31.w));

    // Quad B stores: same channels, pq+32 (adjacent 512B range)
    float4* outqB = outq + 32;
    __stcs(&outqB[0 * PQ], make_float4(B00.x, B10.x, B20.x, B30.x));
    __stcs(&outqB[1 * PQ], make_float4(B00.y, B10.y, B20.y, B30.y));
    __stcs(&outqB[2 * PQ], make_float4(B00.z, B10.z, B20.z, B30.z));
    __stcs(&outqB[3 * PQ], make_float4(B00.w, B10.w, B20.w, B30.w));
    __stcs(&outqB[4 * PQ], make_float4(B01.x, B11.x, B21.x, B31.x));
    __stcs(&outqB[5 * PQ], make_float4(B01.y, B11.y, B21.y, B31.y));
    __stcs(&outqB[6 * PQ], make_float4(B01.z, B11.z, B21.z, B31.z));
    __stcs(&outqB[7 * PQ], make_float4(B01.w, B11.w, B21.w, B31.w));
}

// ---------------------------------------------------------------------------
extern "C" void kernel_launch(void* const* d_in, const int* in_sizes, int n_in,
                              void* d_out, int out_size) {
    const float* feat   = (const float*)d_in[0];   // [N, 64] fp32
    const int*   coords = (const int*)d_in[1];     // [N, 3]  int32
    const int n = in_sizes[0] / CCH;               // number of voxels

    vote_kernel<<<(n + 255) / 256, 256>>>(coords, n);

    int blocks = QTOT / QPB;                       // 4096 blocks x 256 threads
    gather_kernel<<<blocks, 256>>>(feat, (float*)d_out);
}